// round 15
// baseline (speedup 1.0000x reference)
#include <cuda_runtime.h>
#include <math.h>

#define B_DIM   4096
#define C_DIM   5000
#define G4      1250                 // float4 groups per row
#define THREADS 640
#define BLOCKS  296                  // 2 blocks per SM, single wave
#define GPT     2
#define MAX_LR  14                   // ceil(4096/296)
#define NWARPS  (THREADS / 32)       // 20
#define NREP    4                    // column-accumulator replicas

#define SMEM_DYN (MAX_LR * THREADS * (int)sizeof(float2))   // 71680 B

// cross-block column accumulators: (all, pos); neg = all - pos at finalize
__device__ __align__(16) float4 g_col_all[NREP][G4];
__device__ __align__(16) float4 g_col_pos[NREP][G4];
__device__ float g_blk_rowloss[BLOCKS];
__device__ unsigned int g_done;      // zero-init; last block resets

__device__ __forceinline__ float softplus_f(float z) {
    return (z > 20.f) ? z : log1pf(__expf(z));
}

// vectorized global float reduction (sm_90+): one op, 16 bytes
__device__ __forceinline__ void red_v4(float4* addr, const float* v) {
    asm volatile("red.global.add.v4.f32 [%0], {%1, %2, %3, %4};"
                 :: "l"(addr), "f"(v[0]), "f"(v[1]), "f"(v[2]), "f"(v[3])
                 : "memory");
}

#define L2E 1.44269504088896f

// targets are {0,1}. 8 ops/element:
//   tf  = IMAD       (exact 0.0f / 1.0f)
//   m   = FFMA       (log2e  or  -0.25*log2e)
//   y   = FMUL, e = EX2(y)   -> e = exp(x) (neg) or exp(-x/4) (pos)
//   ra += e, ca += e (FADD), rp/cp fma(e,tf,·)
__device__ __forceinline__ void elem_f(float x, int tt,
                                       float& ra, float& rp,
                                       float& cak, float& cpk) {
    const float tf = __int_as_float(tt * 0x3f800000);
    const float m  = fmaf(tf, -1.25f * L2E, L2E);
    float e;
    asm("ex2.approx.ftz.f32 %0, %1;" : "=f"(e) : "f"(x * m));
    ra  += e;
    cak += e;
    rp  = fmaf(e, tf, rp);
    cpk = fmaf(e, tf, cpk);
}

__global__ __launch_bounds__(THREADS, 2)
void twl_fused_kernel(const float* __restrict__ logits,
                      const int*   __restrict__ targets,
                      float* __restrict__ out) {
    extern __shared__ float2 s_part[];           // [MAX_LR][THREADS] = (all, pos)
    __shared__ float s_loss[MAX_LR];
    __shared__ unsigned int s_ticket;
    __shared__ double s_red[NWARPS];

    const int t    = threadIdx.x;
    const int warp = t >> 5;
    const int lane = t & 31;
    const int bid  = blockIdx.x;

    const int  g0   = t;                  // always < 1250
    const int  g1   = t + THREADS;
    const bool has1 = (g1 < G4);

    const int nrows = (B_DIM - bid + BLOCKS - 1) / BLOCKS;   // 13 or 14

    float ca[GPT][4], cp[GPT][4];
    #pragma unroll
    for (int j = 0; j < GPT; ++j)
        #pragma unroll
        for (int k = 0; k < 4; ++k) { ca[j][k] = 0.f; cp[j][k] = 0.f; }

    // flush current accumulators into this block's replica, then zero them
    auto flush_cols = [&]() {
        float4* __restrict__ rep_a = g_col_all[bid & (NREP - 1)];
        float4* __restrict__ rep_p = g_col_pos[bid & (NREP - 1)];
        #pragma unroll
        for (int j = 0; j < GPT; ++j) {
            const int g = t + j * THREADS;
            if (g < G4) {
                red_v4(&rep_a[g], ca[j]);
                red_v4(&rep_p[g], cp[j]);
                #pragma unroll
                for (int k = 0; k < 4; ++k) { ca[j][k] = 0.f; cp[j][k] = 0.f; }
            }
        }
    };

    // prologue: load group 0 of first row (streaming: evict-first)
    int row = bid;
    float4 x0; int4 t0;
    {
        const float4* lr0 = reinterpret_cast<const float4*>(logits + (size_t)row * C_DIM);
        const int4*   tr0 = reinterpret_cast<const int4*>(targets + (size_t)row * C_DIM);
        x0 = __ldcs(&lr0[g0]);
        t0 = __ldcs(&tr0[g0]);
    }

    int lr = 0;
    for (; row < B_DIM; row += BLOCKS, ++lr) {
        const float4* __restrict__ lrow =
            reinterpret_cast<const float4*>(logits + (size_t)row * C_DIM);
        const int4* __restrict__ trow =
            reinterpret_cast<const int4*>(targets + (size_t)row * C_DIM);

        // current row's group-1 load
        float4 x1; int4 t1;
        if (has1) { x1 = __ldcs(&lrow[g1]); t1 = __ldcs(&trow[g1]); }

        // register prefetch: next row's group-0
        const int nrow = row + BLOCKS;
        float4 px; int4 pt;
        if (nrow < B_DIM) {
            const float4* nl = reinterpret_cast<const float4*>(logits + (size_t)nrow * C_DIM);
            const int4*   nt = reinterpret_cast<const int4*>(targets + (size_t)nrow * C_DIM);
            px = __ldcs(&nl[g0]);
            pt = __ldcs(&nt[g0]);
        }

        float ra = 0.f, rp = 0.f;

        elem_f(x0.x, t0.x, ra, rp, ca[0][0], cp[0][0]);
        elem_f(x0.y, t0.y, ra, rp, ca[0][1], cp[0][1]);
        elem_f(x0.z, t0.z, ra, rp, ca[0][2], cp[0][2]);
        elem_f(x0.w, t0.w, ra, rp, ca[0][3], cp[0][3]);
        if (has1) {
            elem_f(x1.x, t1.x, ra, rp, ca[1][0], cp[1][0]);
            elem_f(x1.y, t1.y, ra, rp, ca[1][1], cp[1][1]);
            elem_f(x1.z, t1.z, ra, rp, ca[1][2], cp[1][2]);
            elem_f(x1.w, t1.w, ra, rp, ca[1][3], cp[1][3]);
        }

        // ONE store instead of a serial shuffle chain
        s_part[lr * THREADS + t] = make_float2(ra, rp);

        // mid-loop flush: these REDs hide under the last ~4 rows of streaming
        if (lr == nrows - 4) flush_cols();

        x0 = px; t0 = pt;   // rotate prefetch
    }

    // final (partial) flush — REDs drain in background during epilogue
    flush_cols();

    __syncthreads();   // s_part complete

    // warp w reduces row w: 640 float2 partials -> row loss
    if (warp < nrows) {
        float va = 0.f, vp = 0.f;
        #pragma unroll
        for (int k = 0; k < THREADS / 32; ++k) {
            const float2 v = s_part[warp * THREADS + lane + 32 * k];
            va += v.x; vp += v.y;
        }
        #pragma unroll
        for (int o = 16; o > 0; o >>= 1) {
            va += __shfl_down_sync(0xffffffffu, va, o);
            vp += __shfl_down_sync(0xffffffffu, vp, o);
        }
        if (lane == 0) {
            const float vn = va - vp;        // neg = all - pos
            float loss = 0.f;
            if (vn > 0.f && vp > 0.f) {
                const float z = __logf(vn) + 4.f * __logf(vp);
                loss = softplus_f(z);
            }
            s_loss[warp] = loss;
        }
    }
    __syncthreads();
    if (warp == 0) {
        float v = (lane < nrows) ? s_loss[lane] : 0.f;
        #pragma unroll
        for (int o = 16; o > 0; o >>= 1)
            v += __shfl_down_sync(0xffffffffu, v, o);
        if (lane == 0) g_blk_rowloss[bid] = v;
    }

    __threadfence();
    __syncthreads();
    if (t == 0) s_ticket = atomicAdd(&g_done, 1u);
    __syncthreads();
    if (s_ticket != BLOCKS - 1) return;

    // ---- last block: finalize ----
    __threadfence();

    double loc = 0.0;
    for (int g = t; g < G4; g += THREADS) {
        float4 sa = make_float4(0.f, 0.f, 0.f, 0.f);
        float4 sp = make_float4(0.f, 0.f, 0.f, 0.f);
        #pragma unroll
        for (int r = 0; r < NREP; ++r) {
            const float4 va = g_col_all[r][g];
            const float4 vp = g_col_pos[r][g];
            sa.x += va.x; sa.y += va.y; sa.z += va.z; sa.w += va.w;
            sp.x += vp.x; sp.y += vp.y; sp.z += vp.z; sp.w += vp.w;
            g_col_all[r][g] = make_float4(0.f, 0.f, 0.f, 0.f);
            g_col_pos[r][g] = make_float4(0.f, 0.f, 0.f, 0.f);
        }
        const float a4[4] = {sa.x, sa.y, sa.z, sa.w};
        const float p4[4] = {sp.x, sp.y, sp.z, sp.w};
        #pragma unroll
        for (int k = 0; k < 4; ++k) {
            const float n = a4[k] - p4[k];   // neg = all - pos
            if (n > 0.f && p4[k] > 0.f) {
                const float z = __logf(n) + 4.f * __logf(p4[k]);
                loc += (double)softplus_f(z);
            }
        }
    }
    double rs = 0.0;
    for (int b = t; b < BLOCKS; b += THREADS)
        rs += (double)g_blk_rowloss[b];

    #pragma unroll
    for (int o = 16; o > 0; o >>= 1) {
        loc += __shfl_down_sync(0xffffffffu, loc, o);
        rs  += __shfl_down_sync(0xffffffffu, rs, o);
    }
    if (lane == 0) s_red[warp] = loc;
    __syncthreads();
    double loc_tot = 0.0;
    if (warp == 0 && lane == 0) {
        #pragma unroll
        for (int w = 0; w < NWARPS; ++w) loc_tot += s_red[w];
    }
    __syncthreads();
    if (lane == 0) s_red[warp] = rs;
    __syncthreads();
    if (warp == 0 && lane == 0) {
        double r = 0.0;
        #pragma unroll
        for (int w = 0; w < NWARPS; ++w) r += s_red[w];
        out[0] = (float)(0.5 * (r / (double)B_DIM + loc_tot / (double)C_DIM));
        g_done = 0u;
    }
}

extern "C" void kernel_launch(void* const* d_in, const int* in_sizes, int n_in,
                              void* d_out, int out_size) {
    const float* logits  = (const float*)d_in[0];
    const int*   targets = (const int*)d_in[1];
    float* out = (float*)d_out;

    cudaFuncSetAttribute(twl_fused_kernel,
                         cudaFuncAttributeMaxDynamicSharedMemorySize, SMEM_DYN);
    twl_fused_kernel<<<BLOCKS, THREADS, SMEM_DYN>>>(logits, targets, out);
}

// round 17
// speedup vs baseline: 1.0938x; 1.0938x over previous
#include <cuda_runtime.h>
#include <math.h>

#define B_DIM   4096
#define C_DIM   5000
#define G4      1250                 // float4 groups per row
#define THREADS 640
#define BLOCKS  296                  // 2 blocks per SM, single wave
#define GPT     2
#define MAX_LR  14                   // ceil(4096/296)
#define NWARPS  (THREADS / 32)       // 20
#define NREP    4                    // column-accumulator replicas

#define SMEM_DYN (MAX_LR * THREADS * (int)sizeof(float2))   // 71680 B

// cross-block column accumulators: (all, pos); neg = all - pos at finalize
__device__ __align__(16) float4 g_col_all[NREP][G4];
__device__ __align__(16) float4 g_col_pos[NREP][G4];
__device__ float g_blk_rowloss[BLOCKS];
__device__ unsigned int g_done;      // zero-init; last block resets

__device__ __forceinline__ float softplus_f(float z) {
    return (z > 20.f) ? z : log1pf(__expf(z));
}

// vectorized global float reduction (sm_90+): one op, 16 bytes
__device__ __forceinline__ void red_v4(float4* addr, const float* v) {
    asm volatile("red.global.add.v4.f32 [%0], {%1, %2, %3, %4};"
                 :: "l"(addr), "f"(v[0]), "f"(v[1]), "f"(v[2]), "f"(v[3])
                 : "memory");
}

#define L2E 1.44269504088896f

// targets are {0,1}. 8 ops/element:
//   tf = IMAD (exact 0.0f/1.0f); m = FFMA (log2e or -0.25*log2e)
//   e = EX2(x*m); ra += e; ca += e; rp/cp via FFMA(e,tf,·)
__device__ __forceinline__ void elem_f(float x, int tt,
                                       float& ra, float& rp,
                                       float& cak, float& cpk) {
    const float tf = __int_as_float(tt * 0x3f800000);
    const float m  = fmaf(tf, -1.25f * L2E, L2E);
    float e;
    asm("ex2.approx.ftz.f32 %0, %1;" : "=f"(e) : "f"(x * m));
    ra  += e;
    cak += e;
    rp  = fmaf(e, tf, rp);
    cpk = fmaf(e, tf, cpk);
}

__global__ __launch_bounds__(THREADS, 2)
void twl_fused_kernel(const float* __restrict__ logits,
                      const int*   __restrict__ targets,
                      float* __restrict__ out) {
    extern __shared__ float2 s_part[];           // [MAX_LR][THREADS] = (all, pos)
    __shared__ float s_loss[MAX_LR];
    __shared__ unsigned int s_ticket;
    __shared__ double s_red[NWARPS];

    const int t    = threadIdx.x;
    const int warp = t >> 5;
    const int lane = t & 31;
    const int bid  = blockIdx.x;

    const int  g0   = t;                  // always < 1250
    const int  g1   = t + THREADS;
    const bool has1 = (g1 < G4);

    const int nrows = (B_DIM - bid + BLOCKS - 1) / BLOCKS;   // 13 or 14

    float ca[GPT][4], cp[GPT][4];
    #pragma unroll
    for (int j = 0; j < GPT; ++j)
        #pragma unroll
        for (int k = 0; k < 4; ++k) { ca[j][k] = 0.f; cp[j][k] = 0.f; }

    // flush current accumulators into this block's replica, then zero them
    auto flush_cols = [&]() {
        float4* __restrict__ rep_a = g_col_all[bid & (NREP - 1)];
        float4* __restrict__ rep_p = g_col_pos[bid & (NREP - 1)];
        #pragma unroll
        for (int j = 0; j < GPT; ++j) {
            const int g = t + j * THREADS;
            if (g < G4) {
                red_v4(&rep_a[g], ca[j]);
                red_v4(&rep_p[g], cp[j]);
                #pragma unroll
                for (int k = 0; k < 4; ++k) { ca[j][k] = 0.f; cp[j][k] = 0.f; }
            }
        }
    };

    // prologue: load group 0 of first row (plain LDG — R13 load path)
    int row = bid;
    float4 x0; int4 t0;
    {
        const float4* lr0 = reinterpret_cast<const float4*>(logits + (size_t)row * C_DIM);
        const int4*   tr0 = reinterpret_cast<const int4*>(targets + (size_t)row * C_DIM);
        x0 = lr0[g0];
        t0 = tr0[g0];
    }

    int lr = 0;
    for (; row < B_DIM; row += BLOCKS, ++lr) {
        const float4* __restrict__ lrow =
            reinterpret_cast<const float4*>(logits + (size_t)row * C_DIM);
        const int4* __restrict__ trow =
            reinterpret_cast<const int4*>(targets + (size_t)row * C_DIM);

        // current row's group-1 load
        float4 x1; int4 t1;
        if (has1) { x1 = lrow[g1]; t1 = trow[g1]; }

        // register prefetch: next row's group-0
        const int nrow = row + BLOCKS;
        float4 px; int4 pt;
        if (nrow < B_DIM) {
            const float4* nl = reinterpret_cast<const float4*>(logits + (size_t)nrow * C_DIM);
            const int4*   nt = reinterpret_cast<const int4*>(targets + (size_t)nrow * C_DIM);
            px = nl[g0];
            pt = nt[g0];
        }

        float ra = 0.f, rp = 0.f;

        elem_f(x0.x, t0.x, ra, rp, ca[0][0], cp[0][0]);
        elem_f(x0.y, t0.y, ra, rp, ca[0][1], cp[0][1]);
        elem_f(x0.z, t0.z, ra, rp, ca[0][2], cp[0][2]);
        elem_f(x0.w, t0.w, ra, rp, ca[0][3], cp[0][3]);
        if (has1) {
            elem_f(x1.x, t1.x, ra, rp, ca[1][0], cp[1][0]);
            elem_f(x1.y, t1.y, ra, rp, ca[1][1], cp[1][1]);
            elem_f(x1.z, t1.z, ra, rp, ca[1][2], cp[1][2]);
            elem_f(x1.w, t1.w, ra, rp, ca[1][3], cp[1][3]);
        }

        // ONE store instead of a serial shuffle chain
        s_part[lr * THREADS + t] = make_float2(ra, rp);

        // mid-loop flush: these REDs hide under the last ~4 rows of streaming
        if (lr == nrows - 4) flush_cols();

        x0 = px; t0 = pt;   // rotate prefetch
    }

    // final (partial) flush — REDs drain in background during epilogue
    flush_cols();

    __syncthreads();   // s_part complete

    // warp w reduces row w: 640 float2 partials -> row loss
    if (warp < nrows) {
        float va = 0.f, vp = 0.f;
        #pragma unroll
        for (int k = 0; k < THREADS / 32; ++k) {
            const float2 v = s_part[warp * THREADS + lane + 32 * k];
            va += v.x; vp += v.y;
        }
        #pragma unroll
        for (int o = 16; o > 0; o >>= 1) {
            va += __shfl_down_sync(0xffffffffu, va, o);
            vp += __shfl_down_sync(0xffffffffu, vp, o);
        }
        if (lane == 0) {
            const float vn = va - vp;        // neg = all - pos
            float loss = 0.f;
            if (vn > 0.f && vp > 0.f) {
                const float z = __logf(vn) + 4.f * __logf(vp);
                loss = softplus_f(z);
            }
            s_loss[warp] = loss;
        }
    }
    __syncthreads();
    if (warp == 0) {
        float v = (lane < nrows) ? s_loss[lane] : 0.f;
        #pragma unroll
        for (int o = 16; o > 0; o >>= 1)
            v += __shfl_down_sync(0xffffffffu, v, o);
        if (lane == 0) g_blk_rowloss[bid] = v;
    }

    __threadfence();
    __syncthreads();
    if (t == 0) s_ticket = atomicAdd(&g_done, 1u);
    __syncthreads();
    if (s_ticket != BLOCKS - 1) return;

    // ---- last block: finalize ----
    __threadfence();

    double loc = 0.0;
    for (int g = t; g < G4; g += THREADS) {
        float4 sa = make_float4(0.f, 0.f, 0.f, 0.f);
        float4 sp = make_float4(0.f, 0.f, 0.f, 0.f);
        #pragma unroll
        for (int r = 0; r < NREP; ++r) {
            const float4 va = g_col_all[r][g];
            const float4 vp = g_col_pos[r][g];
            sa.x += va.x; sa.y += va.y; sa.z += va.z; sa.w += va.w;
            sp.x += vp.x; sp.y += vp.y; sp.z += vp.z; sp.w += vp.w;
            g_col_all[r][g] = make_float4(0.f, 0.f, 0.f, 0.f);
            g_col_pos[r][g] = make_float4(0.f, 0.f, 0.f, 0.f);
        }
        const float a4[4] = {sa.x, sa.y, sa.z, sa.w};
        const float p4[4] = {sp.x, sp.y, sp.z, sp.w};
        #pragma unroll
        for (int k = 0; k < 4; ++k) {
            const float n = a4[k] - p4[k];   // neg = all - pos
            if (n > 0.f && p4[k] > 0.f) {
                const float z = __logf(n) + 4.f * __logf(p4[k]);
                loc += (double)softplus_f(z);
            }
        }
    }
    double rs = 0.0;
    for (int b = t; b < BLOCKS; b += THREADS)
        rs += (double)g_blk_rowloss[b];

    #pragma unroll
    for (int o = 16; o > 0; o >>= 1) {
        loc += __shfl_down_sync(0xffffffffu, loc, o);
        rs  += __shfl_down_sync(0xffffffffu, rs, o);
    }
    if (lane == 0) s_red[warp] = loc;
    __syncthreads();
    double loc_tot = 0.0;
    if (warp == 0 && lane == 0) {
        #pragma unroll
        for (int w = 0; w < NWARPS; ++w) loc_tot += s_red[w];
    }
    __syncthreads();
    if (lane == 0) s_red[warp] = rs;
    __syncthreads();
    if (warp == 0 && lane == 0) {
        double r = 0.0;
        #pragma unroll
        for (int w = 0; w < NWARPS; ++w) r += s_red[w];
        out[0] = (float)(0.5 * (r / (double)B_DIM + loc_tot / (double)C_DIM));
        g_done = 0u;
    }
}

extern "C" void kernel_launch(void* const* d_in, const int* in_sizes, int n_in,
                              void* d_out, int out_size) {
    const float* logits  = (const float*)d_in[0];
    const int*   targets = (const int*)d_in[1];
    float* out = (float*)d_out;

    cudaFuncSetAttribute(twl_fused_kernel,
                         cudaFuncAttributeMaxDynamicSharedMemorySize, SMEM_DYN);
    twl_fused_kernel<<<BLOCKS, THREADS, SMEM_DYN>>>(logits, targets, out);
}